// round 1
// baseline (speedup 1.0000x reference)
#include <cuda_runtime.h>
#include <math.h>

// Problem constants (from reference): B=1, S=4096, EMBED=768, HEADS=12, HDIM=64
#define S_LEN 4096
#define EMBED 768
#define HEADS 12
#define HDIM  64

// Scratch (allocation-free rule: __device__ globals)
__device__ __align__(16) float g_Q[S_LEN * EMBED];
__device__ __align__(16) float g_K[S_LEN * EMBED];
__device__ __align__(16) float g_V[S_LEN * EMBED];
__device__ __align__(16) float g_O[S_LEN * EMBED];

// ---------------------------------------------------------------------------
// Tiled fp32 GEMM: C[M,N] = A[M,K] @ B[K,N] (+ bias). 128x128 tile, KT=16,
// 256 threads, 8x8 register micro-tile. Dims assumed multiples of tile sizes
// (4096/768 are).
// ---------------------------------------------------------------------------
__global__ __launch_bounds__(256)
void gemm128_kernel(const float* __restrict__ A, const float* __restrict__ B,
                    float* __restrict__ C, const float* __restrict__ bias,
                    int M, int N, int K)
{
    __shared__ float As[16][128];   // transposed A tile: As[k][m]
    __shared__ float Bs[16][128];   // Bs[k][n]

    const int t  = threadIdx.x;
    const int tx = t & 15;          // 0..15 -> 8 output cols each
    const int ty = t >> 4;          // 0..15 -> 8 output rows each
    const int bx = blockIdx.x;      // N tile
    const int by = blockIdx.y;      // M tile

    float acc[8][8];
#pragma unroll
    for (int i = 0; i < 8; i++)
#pragma unroll
        for (int j = 0; j < 8; j++) acc[i][j] = 0.f;

    for (int k0 = 0; k0 < K; k0 += 16) {
        __syncthreads();
#pragma unroll
        for (int u = 0; u < 2; u++) {
            int id = t + u * 256;              // 0..511 float4 slots
            int r  = id >> 2, c4 = id & 3;     // A: 128 rows x 4 float4
            float4 av = *(const float4*)&A[(size_t)(by * 128 + r) * K + k0 + c4 * 4];
            As[c4 * 4 + 0][r] = av.x;
            As[c4 * 4 + 1][r] = av.y;
            As[c4 * 4 + 2][r] = av.z;
            As[c4 * 4 + 3][r] = av.w;
            int rb = id >> 5, cb = id & 31;    // B: 16 rows x 32 float4
            *(float4*)&Bs[rb][cb * 4] =
                *(const float4*)&B[(size_t)(k0 + rb) * N + bx * 128 + cb * 4];
        }
        __syncthreads();
#pragma unroll
        for (int kk = 0; kk < 16; kk++) {
            float a[8], b[8];
            *(float4*)&a[0] = *(const float4*)&As[kk][ty * 8];
            *(float4*)&a[4] = *(const float4*)&As[kk][ty * 8 + 4];
            *(float4*)&b[0] = *(const float4*)&Bs[kk][tx * 8];
            *(float4*)&b[4] = *(const float4*)&Bs[kk][tx * 8 + 4];
#pragma unroll
            for (int i = 0; i < 8; i++)
#pragma unroll
                for (int j = 0; j < 8; j++)
                    acc[i][j] = fmaf(a[i], b[j], acc[i][j]);
        }
    }

#pragma unroll
    for (int i = 0; i < 8; i++) {
        int row = by * 128 + ty * 8 + i;
#pragma unroll
        for (int j4 = 0; j4 < 2; j4++) {
            int col = bx * 128 + tx * 8 + j4 * 4;
            float4 o;
            o.x = acc[i][j4 * 4 + 0];
            o.y = acc[i][j4 * 4 + 1];
            o.z = acc[i][j4 * 4 + 2];
            o.w = acc[i][j4 * 4 + 3];
            if (bias) {
                o.x += bias[col + 0];
                o.y += bias[col + 1];
                o.z += bias[col + 2];
                o.w += bias[col + 3];
            }
            *(float4*)&C[(size_t)row * N + col] = o;
        }
    }
}

// ---------------------------------------------------------------------------
// Causal flash attention, fp32. Grid: (S/64 q-tiles, 12 heads), 64 threads.
// Thread t owns q-row (qt*64+t): q[64] and acc[64] live in registers.
// K/V tiles (64x64) staged in smem; scores staged transposed in smem
// (Ssm[kk][t] -> lane-consecutive, conflict-free). Causal handled analytically
// (mask*(-1e9) underflows to 0 after softmax in fp32, identical result).
// ---------------------------------------------------------------------------
__global__ __launch_bounds__(64)
void attn_kernel(const float* __restrict__ Q, const float* __restrict__ K,
                 const float* __restrict__ V, float* __restrict__ O)
{
    __shared__ float Ksm[64 * 64];
    __shared__ float Vsm[64 * 64];
    __shared__ float Ssm[64 * 64];   // [kk][t]

    const int t    = threadIdx.x;     // q row within tile
    const int qt   = blockIdx.x;      // q tile 0..63
    const int h    = blockIdx.y;      // head
    const int qrow = qt * 64 + t;

    // load my q row into registers
    float q[64];
    {
        const float* qp = &Q[(size_t)qrow * EMBED + h * HDIM];
#pragma unroll
        for (int d4 = 0; d4 < 16; d4++) {
            float4 v = *(const float4*)(qp + d4 * 4);
            q[d4 * 4 + 0] = v.x; q[d4 * 4 + 1] = v.y;
            q[d4 * 4 + 2] = v.z; q[d4 * 4 + 3] = v.w;
        }
    }

    float acc[64];
#pragma unroll
    for (int d = 0; d < 64; d++) acc[d] = 0.f;
    float m = -1e30f, l = 0.f;

    for (int j = 0; j <= qt; j++) {
        __syncthreads();
        // cooperative K/V tile load: 1024 float4 per tile, 16 per thread
#pragma unroll
        for (int u = 0; u < 16; u++) {
            int id = t + u * 64;
            int r = id >> 4, c4 = id & 15;
            size_t goff = (size_t)(j * 64 + r) * EMBED + h * HDIM + c4 * 4;
            *(float4*)&Ksm[r * 64 + c4 * 4] = *(const float4*)&K[goff];
            *(float4*)&Vsm[r * 64 + c4 * 4] = *(const float4*)&V[goff];
        }
        __syncthreads();

        const bool diag = (j == qt);
        float tmax = -1e30f;
        for (int kk = 0; kk < 64; kk++) {
            const float4* kr = (const float4*)&Ksm[kk * 64];
            float s0 = 0.f, s1 = 0.f, s2 = 0.f, s3 = 0.f;
#pragma unroll
            for (int d4 = 0; d4 < 16; d4++) {
                float4 kv = kr[d4];
                s0 = fmaf(q[d4 * 4 + 0], kv.x, s0);
                s1 = fmaf(q[d4 * 4 + 1], kv.y, s1);
                s2 = fmaf(q[d4 * 4 + 2], kv.z, s2);
                s3 = fmaf(q[d4 * 4 + 3], kv.w, s3);
            }
            float s = ((s0 + s1) + (s2 + s3)) * 0.125f;   // 1/sqrt(64)
            if (diag && kk > t) s = -1e30f;
            Ssm[kk * 64 + t] = s;
            tmax = fmaxf(tmax, s);
        }

        float m_new = fmaxf(m, tmax);
        float corr  = __expf(m - m_new);
        l *= corr;
#pragma unroll
        for (int d = 0; d < 64; d++) acc[d] *= corr;

        for (int kk = 0; kk < 64; kk++) {
            float p = __expf(Ssm[kk * 64 + t] - m_new);
            l += p;
            const float4* vr = (const float4*)&Vsm[kk * 64];
#pragma unroll
            for (int d4 = 0; d4 < 16; d4++) {
                float4 vv = vr[d4];
                acc[d4 * 4 + 0] = fmaf(p, vv.x, acc[d4 * 4 + 0]);
                acc[d4 * 4 + 1] = fmaf(p, vv.y, acc[d4 * 4 + 1]);
                acc[d4 * 4 + 2] = fmaf(p, vv.z, acc[d4 * 4 + 2]);
                acc[d4 * 4 + 3] = fmaf(p, vv.w, acc[d4 * 4 + 3]);
            }
        }
        m = m_new;
    }

    // epilogue: normalize and store to O[s, h*64 + d]
    float rl = 1.f / l;
    float* op = &O[(size_t)qrow * EMBED + h * HDIM];
#pragma unroll
    for (int d4 = 0; d4 < 16; d4++) {
        float4 o;
        o.x = acc[d4 * 4 + 0] * rl;
        o.y = acc[d4 * 4 + 1] * rl;
        o.z = acc[d4 * 4 + 2] * rl;
        o.w = acc[d4 * 4 + 3] * rl;
        *(float4*)(op + d4 * 4) = o;
    }
}

// ---------------------------------------------------------------------------
// Launch: QKV projections -> causal flash attention -> output projection+bias
// Input order (metadata): values, keys, queries, mask, W_q, W_k, W_v, W_o, b_o
// ---------------------------------------------------------------------------
extern "C" void kernel_launch(void* const* d_in, const int* in_sizes, int n_in,
                              void* d_out, int out_size)
{
    const float* values  = (const float*)d_in[0];
    const float* keys    = (const float*)d_in[1];
    const float* queries = (const float*)d_in[2];
    // d_in[3] = mask: pure causal triu, handled analytically — never read
    const float* W_q = (const float*)d_in[4];
    const float* W_k = (const float*)d_in[5];
    const float* W_v = (const float*)d_in[6];
    const float* W_o = (const float*)d_in[7];
    const float* b_o = (const float*)d_in[8];
    float* out = (float*)d_out;

    float *Qp, *Kp, *Vp, *Op;
    cudaGetSymbolAddress((void**)&Qp, g_Q);
    cudaGetSymbolAddress((void**)&Kp, g_K);
    cudaGetSymbolAddress((void**)&Vp, g_V);
    cudaGetSymbolAddress((void**)&Op, g_O);

    dim3 gemm_grid(EMBED / 128, S_LEN / 128);   // (6, 32)
    gemm128_kernel<<<gemm_grid, 256>>>(queries, W_q, Qp, nullptr, S_LEN, EMBED, EMBED);
    gemm128_kernel<<<gemm_grid, 256>>>(keys,    W_k, Kp, nullptr, S_LEN, EMBED, EMBED);
    gemm128_kernel<<<gemm_grid, 256>>>(values,  W_v, Vp, nullptr, S_LEN, EMBED, EMBED);

    dim3 attn_grid(S_LEN / 64, HEADS);          // (64, 12)
    attn_kernel<<<attn_grid, 64>>>(Qp, Kp, Vp, Op);

    gemm128_kernel<<<gemm_grid, 256>>>(Op, W_o, out, b_o, S_LEN, EMBED, EMBED);
}

// round 2
// speedup vs baseline: 2.0726x; 2.0726x over previous
#include <cuda_runtime.h>
#include <math.h>
#include <stdint.h>

// Problem constants: B=1, S=4096, EMBED=768, HEADS=12, HDIM=64
#define S_LEN 4096
#define EMBED 768
#define HEADS 12
#define HDIM  64

// Scratch (allocation-free rule: __device__ globals)
__device__ __align__(16) float g_Q[S_LEN * EMBED];
__device__ __align__(16) float g_K[S_LEN * EMBED];
__device__ __align__(16) float g_V[S_LEN * EMBED];
__device__ __align__(16) float g_O[S_LEN * EMBED];

// ---------------------------------------------------------------------------
// Tiled fp32 GEMM (unchanged from round 1): C[M,N] = A[M,K] @ B[K,N] (+bias)
// ---------------------------------------------------------------------------
__global__ __launch_bounds__(256)
void gemm128_kernel(const float* __restrict__ A, const float* __restrict__ B,
                    float* __restrict__ C, const float* __restrict__ bias,
                    int M, int N, int K)
{
    __shared__ float As[16][128];
    __shared__ float Bs[16][128];

    const int t  = threadIdx.x;
    const int tx = t & 15;
    const int ty = t >> 4;
    const int bx = blockIdx.x;
    const int by = blockIdx.y;

    float acc[8][8];
#pragma unroll
    for (int i = 0; i < 8; i++)
#pragma unroll
        for (int j = 0; j < 8; j++) acc[i][j] = 0.f;

    for (int k0 = 0; k0 < K; k0 += 16) {
        __syncthreads();
#pragma unroll
        for (int u = 0; u < 2; u++) {
            int id = t + u * 256;
            int r  = id >> 2, c4 = id & 3;
            float4 av = *(const float4*)&A[(size_t)(by * 128 + r) * K + k0 + c4 * 4];
            As[c4 * 4 + 0][r] = av.x;
            As[c4 * 4 + 1][r] = av.y;
            As[c4 * 4 + 2][r] = av.z;
            As[c4 * 4 + 3][r] = av.w;
            int rb = id >> 5, cb = id & 31;
            *(float4*)&Bs[rb][cb * 4] =
                *(const float4*)&B[(size_t)(k0 + rb) * N + bx * 128 + cb * 4];
        }
        __syncthreads();
#pragma unroll
        for (int kk = 0; kk < 16; kk++) {
            float a[8], b[8];
            *(float4*)&a[0] = *(const float4*)&As[kk][ty * 8];
            *(float4*)&a[4] = *(const float4*)&As[kk][ty * 8 + 4];
            *(float4*)&b[0] = *(const float4*)&Bs[kk][tx * 8];
            *(float4*)&b[4] = *(const float4*)&Bs[kk][tx * 8 + 4];
#pragma unroll
            for (int i = 0; i < 8; i++)
#pragma unroll
                for (int j = 0; j < 8; j++)
                    acc[i][j] = fmaf(a[i], b[j], acc[i][j]);
        }
    }

#pragma unroll
    for (int i = 0; i < 8; i++) {
        int row = by * 128 + ty * 8 + i;
#pragma unroll
        for (int j4 = 0; j4 < 2; j4++) {
            int col = bx * 128 + tx * 8 + j4 * 4;
            float4 o;
            o.x = acc[i][j4 * 4 + 0];
            o.y = acc[i][j4 * 4 + 1];
            o.z = acc[i][j4 * 4 + 2];
            o.w = acc[i][j4 * 4 + 3];
            if (bias) {
                o.x += bias[col + 0];
                o.y += bias[col + 1];
                o.z += bias[col + 2];
                o.w += bias[col + 3];
            }
            *(float4*)&C[(size_t)row * N + col] = o;
        }
    }
}

// ---------------------------------------------------------------------------
// tf32 tensor-core helpers
// ---------------------------------------------------------------------------
__device__ __forceinline__ uint32_t f2tf32(float x) {
    uint32_t r;
    asm("cvt.rna.tf32.f32 %0, %1;" : "=r"(r) : "f"(x));
    return r;
}

struct FragC { float x, y, z, w; };

__device__ __forceinline__ void mma_tf32(FragC& d,
                                         uint32_t a0, uint32_t a1, uint32_t a2, uint32_t a3,
                                         uint32_t b0, uint32_t b1,
                                         const FragC& c)
{
    asm volatile(
        "mma.sync.aligned.m16n8k8.row.col.f32.tf32.tf32.f32 "
        "{%0,%1,%2,%3}, {%4,%5,%6,%7}, {%8,%9}, {%10,%11,%12,%13};\n"
        : "=f"(d.x), "=f"(d.y), "=f"(d.z), "=f"(d.w)
        : "r"(a0), "r"(a1), "r"(a2), "r"(a3), "r"(b0), "r"(b1),
          "f"(c.x), "f"(c.y), "f"(c.z), "f"(c.w));
}

// ---------------------------------------------------------------------------
// Causal flash attention, tf32 tensor cores.
// Grid: (S/64, HEADS), 128 threads (4 warps). Warp w owns q-rows
// [qt*64 + w*16, +16). K/V tiles 64x64 staged in smem (stride 68 = conflict-
// free mma fragment loads). P (probs) reuses the K smem region after QK^T.
// Causal handled analytically.
// ---------------------------------------------------------------------------
#define KVSTRIDE 68

__global__ __launch_bounds__(128)
void attn_tc_kernel(const float* __restrict__ Q, const float* __restrict__ K,
                    const float* __restrict__ V, float* __restrict__ O)
{
    __shared__ float Ksm[64 * KVSTRIDE];   // also reused for P after QK^T
    __shared__ float Vsm[64 * KVSTRIDE];

    const int t    = threadIdx.x;
    const int w    = t >> 5;          // warp 0..3
    const int lane = t & 31;
    const int g    = lane >> 2;       // groupID 0..7
    const int tig  = lane & 3;        // thread-in-group 0..3
    const int qt   = blockIdx.x;
    const int h    = blockIdx.y;

    const int row0 = qt * 64 + w * 16 + g;   // global q row (and row0+8)
    const int row1 = row0 + 8;

    // ---- Q fragments (resident, tf32) : 8 k-chunks x 4 regs ----
    uint32_t qa[8][4];
    {
        const float* q0 = &Q[(size_t)row0 * EMBED + h * HDIM];
        const float* q1 = &Q[(size_t)row1 * EMBED + h * HDIM];
#pragma unroll
        for (int kc = 0; kc < 8; kc++) {
            qa[kc][0] = f2tf32(q0[kc * 8 + tig]);
            qa[kc][1] = f2tf32(q1[kc * 8 + tig]);
            qa[kc][2] = f2tf32(q0[kc * 8 + tig + 4]);
            qa[kc][3] = f2tf32(q1[kc * 8 + tig + 4]);
        }
    }

    FragC oacc[8];
#pragma unroll
    for (int nc = 0; nc < 8; nc++) { oacc[nc].x = oacc[nc].y = oacc[nc].z = oacc[nc].w = 0.f; }
    float m0 = -1e30f, m1 = -1e30f, l0 = 0.f, l1 = 0.f;

    for (int j = 0; j <= qt; j++) {
        __syncthreads();   // prior iteration's Psm/Vsm reads complete

        // ---- cooperative K/V tile load + tf32 conversion ----
#pragma unroll
        for (int u = 0; u < 8; u++) {
            int id = t + u * 128;
            int r  = id >> 4;
            int c  = (id & 15) * 4;
            size_t goff = (size_t)(j * 64 + r) * EMBED + h * HDIM + c;
            float4 kv = *(const float4*)&K[goff];
            float4 vv = *(const float4*)&V[goff];
            float4 kc4, vc4;
            kc4.x = __uint_as_float(f2tf32(kv.x));
            kc4.y = __uint_as_float(f2tf32(kv.y));
            kc4.z = __uint_as_float(f2tf32(kv.z));
            kc4.w = __uint_as_float(f2tf32(kv.w));
            vc4.x = __uint_as_float(f2tf32(vv.x));
            vc4.y = __uint_as_float(f2tf32(vv.y));
            vc4.z = __uint_as_float(f2tf32(vv.z));
            vc4.w = __uint_as_float(f2tf32(vv.w));
            *(float4*)&Ksm[r * KVSTRIDE + c] = kc4;
            *(float4*)&Vsm[r * KVSTRIDE + c] = vc4;
        }
        __syncthreads();

        // ---- S = Q K^T (16x64 per warp) ----
        FragC st[8];
#pragma unroll
        for (int nc = 0; nc < 8; nc++) { st[nc].x = st[nc].y = st[nc].z = st[nc].w = 0.f; }
#pragma unroll
        for (int kc = 0; kc < 8; kc++) {
            const int d0 = kc * 8 + tig;
#pragma unroll
            for (int nc = 0; nc < 8; nc++) {
                const float* kr = &Ksm[(nc * 8 + g) * KVSTRIDE];
                uint32_t b0 = __float_as_uint(kr[d0]);
                uint32_t b1 = __float_as_uint(kr[d0 + 4]);
                mma_tf32(st[nc], qa[kc][0], qa[kc][1], qa[kc][2], qa[kc][3], b0, b1, st[nc]);
            }
        }

        __syncthreads();   // all warps done reading Ksm before P overwrites it

        // ---- scale + causal mask + online softmax ----
        const bool diag = (j == qt);
        const int colb = j * 64 + 2 * tig;
        float tmax0 = -1e30f, tmax1 = -1e30f;
#pragma unroll
        for (int nc = 0; nc < 8; nc++) {
            int c0 = colb + nc * 8;
            float sx = st[nc].x * 0.125f;
            float sy = st[nc].y * 0.125f;
            float sz = st[nc].z * 0.125f;
            float sw = st[nc].w * 0.125f;
            if (diag) {
                if (c0     > row0) sx = -1e30f;
                if (c0 + 1 > row0) sy = -1e30f;
                if (c0     > row1) sz = -1e30f;
                if (c0 + 1 > row1) sw = -1e30f;
            }
            st[nc].x = sx; st[nc].y = sy; st[nc].z = sz; st[nc].w = sw;
            tmax0 = fmaxf(tmax0, fmaxf(sx, sy));
            tmax1 = fmaxf(tmax1, fmaxf(sz, sw));
        }
        tmax0 = fmaxf(tmax0, __shfl_xor_sync(0xffffffff, tmax0, 1));
        tmax0 = fmaxf(tmax0, __shfl_xor_sync(0xffffffff, tmax0, 2));
        tmax1 = fmaxf(tmax1, __shfl_xor_sync(0xffffffff, tmax1, 1));
        tmax1 = fmaxf(tmax1, __shfl_xor_sync(0xffffffff, tmax1, 2));

        float m0n = fmaxf(m0, tmax0);
        float m1n = fmaxf(m1, tmax1);
        float cr0 = __expf(m0 - m0n);
        float cr1 = __expf(m1 - m1n);
        m0 = m0n; m1 = m1n;
        l0 *= cr0; l1 *= cr1;
#pragma unroll
        for (int nc = 0; nc < 8; nc++) {
            oacc[nc].x *= cr0; oacc[nc].y *= cr0;
            oacc[nc].z *= cr1; oacc[nc].w *= cr1;
        }

        float sum0 = 0.f, sum1 = 0.f;
        float* Pw0 = &Ksm[(w * 16 + g) * KVSTRIDE];       // P row for row0
        float* Pw1 = &Ksm[(w * 16 + g + 8) * KVSTRIDE];   // P row for row1
#pragma unroll
        for (int nc = 0; nc < 8; nc++) {
            float px = __expf(st[nc].x - m0n);
            float py = __expf(st[nc].y - m0n);
            float pz = __expf(st[nc].z - m1n);
            float pw = __expf(st[nc].w - m1n);
            sum0 += px + py;
            sum1 += pz + pw;
            float2 p01, p23;
            p01.x = __uint_as_float(f2tf32(px));
            p01.y = __uint_as_float(f2tf32(py));
            p23.x = __uint_as_float(f2tf32(pz));
            p23.y = __uint_as_float(f2tf32(pw));
            *(float2*)&Pw0[nc * 8 + 2 * tig] = p01;
            *(float2*)&Pw1[nc * 8 + 2 * tig] = p23;
        }
        sum0 += __shfl_xor_sync(0xffffffff, sum0, 1);
        sum0 += __shfl_xor_sync(0xffffffff, sum0, 2);
        sum1 += __shfl_xor_sync(0xffffffff, sum1, 1);
        sum1 += __shfl_xor_sync(0xffffffff, sum1, 2);
        l0 += sum0; l1 += sum1;

        __syncwarp();   // P visible within the warp

        // ---- O += P V  (A = own-warp P rows, B = Vsm) ----
        const float* P0 = &Ksm[(w * 16 + g) * KVSTRIDE];
        const float* P1 = &Ksm[(w * 16 + g + 8) * KVSTRIDE];
#pragma unroll
        for (int kc = 0; kc < 8; kc++) {
            uint32_t a0 = __float_as_uint(P0[kc * 8 + tig]);
            uint32_t a1 = __float_as_uint(P1[kc * 8 + tig]);
            uint32_t a2 = __float_as_uint(P0[kc * 8 + tig + 4]);
            uint32_t a3 = __float_as_uint(P1[kc * 8 + tig + 4]);
            const float* vr0 = &Vsm[(kc * 8 + tig) * KVSTRIDE];
            const float* vr1 = &Vsm[(kc * 8 + tig + 4) * KVSTRIDE];
#pragma unroll
            for (int nc = 0; nc < 8; nc++) {
                uint32_t b0 = __float_as_uint(vr0[nc * 8 + g]);
                uint32_t b1 = __float_as_uint(vr1[nc * 8 + g]);
                mma_tf32(oacc[nc], a0, a1, a2, a3, b0, b1, oacc[nc]);
            }
        }
    }

    // ---- epilogue: normalize and store ----
    float r0 = 1.f / l0;
    float r1 = 1.f / l1;
    float* o0 = &O[(size_t)row0 * EMBED + h * HDIM];
    float* o1 = &O[(size_t)row1 * EMBED + h * HDIM];
#pragma unroll
    for (int nc = 0; nc < 8; nc++) {
        float2 a, b;
        a.x = oacc[nc].x * r0; a.y = oacc[nc].y * r0;
        b.x = oacc[nc].z * r1; b.y = oacc[nc].w * r1;
        *(float2*)&o0[nc * 8 + 2 * tig] = a;
        *(float2*)&o1[nc * 8 + 2 * tig] = b;
    }
}

// ---------------------------------------------------------------------------
// Launch. Input order: values, keys, queries, mask, W_q, W_k, W_v, W_o, b_o
// ---------------------------------------------------------------------------
extern "C" void kernel_launch(void* const* d_in, const int* in_sizes, int n_in,
                              void* d_out, int out_size)
{
    const float* values  = (const float*)d_in[0];
    const float* keys    = (const float*)d_in[1];
    const float* queries = (const float*)d_in[2];
    // d_in[3] = mask: pure causal triu, handled analytically — never read
    const float* W_q = (const float*)d_in[4];
    const float* W_k = (const float*)d_in[5];
    const float* W_v = (const float*)d_in[6];
    const float* W_o = (const float*)d_in[7];
    const float* b_o = (const float*)d_in[8];
    float* out = (float*)d_out;

    float *Qp, *Kp, *Vp, *Op;
    cudaGetSymbolAddress((void**)&Qp, g_Q);
    cudaGetSymbolAddress((void**)&Kp, g_K);
    cudaGetSymbolAddress((void**)&Vp, g_V);
    cudaGetSymbolAddress((void**)&Op, g_O);

    dim3 gemm_grid(EMBED / 128, S_LEN / 128);   // (6, 32)
    gemm128_kernel<<<gemm_grid, 256>>>(queries, W_q, Qp, nullptr, S_LEN, EMBED, EMBED);
    gemm128_kernel<<<gemm_grid, 256>>>(keys,    W_k, Kp, nullptr, S_LEN, EMBED, EMBED);
    gemm128_kernel<<<gemm_grid, 256>>>(values,  W_v, Vp, nullptr, S_LEN, EMBED, EMBED);

    dim3 attn_grid(S_LEN / 64, HEADS);          // (64, 12)
    attn_tc_kernel<<<attn_grid, 128>>>(Qp, Kp, Vp, Op);

    gemm128_kernel<<<gemm_grid, 256>>>(Op, W_o, out, b_o, S_LEN, EMBED, EMBED);
}

// round 4
// speedup vs baseline: 2.1863x; 1.0549x over previous
#include <cuda_runtime.h>
#include <math.h>
#include <stdint.h>

// Problem constants: B=1, S=4096, EMBED=768, HEADS=12, HDIM=64
#define S_LEN 4096
#define EMBED 768
#define HEADS 12
#define HDIM  64

// Scratch (allocation-free rule: __device__ globals)
__device__ __align__(16) float g_Q[S_LEN * EMBED];
__device__ __align__(16) float g_K[S_LEN * EMBED];
__device__ __align__(16) float g_V[S_LEN * EMBED];
__device__ __align__(16) float g_O[S_LEN * EMBED];

// ---------------------------------------------------------------------------
// tf32 helpers
// ---------------------------------------------------------------------------
__device__ __forceinline__ uint32_t f2tf32(float x) {
    uint32_t r;
    asm("cvt.rna.tf32.f32 %0, %1;" : "=r"(r) : "f"(x));
    return r;
}

struct FragC { float x, y, z, w; };

__device__ __forceinline__ void mma_tf32(FragC& d,
                                         uint32_t a0, uint32_t a1, uint32_t a2, uint32_t a3,
                                         uint32_t b0, uint32_t b1,
                                         const FragC& c)
{
    asm volatile(
        "mma.sync.aligned.m16n8k8.row.col.f32.tf32.tf32.f32 "
        "{%0,%1,%2,%3}, {%4,%5,%6,%7}, {%8,%9}, {%10,%11,%12,%13};\n"
        : "=f"(d.x), "=f"(d.y), "=f"(d.z), "=f"(d.w)
        : "r"(a0), "r"(a1), "r"(a2), "r"(a3), "r"(b0), "r"(b1),
          "f"(c.x), "f"(c.y), "f"(c.z), "f"(c.w));
}

// ---------------------------------------------------------------------------
// 3xTF32 tensor-core GEMM: C[M,N] = A[M,K] @ B[K,N] (+bias), fp32-accurate.
// CTA tile 128(M) x 64(N), KT=16, 256 threads = 8 warps (4 m x 2 n),
// warp tile 32x32. a = a_hi + a_lo (tf32 split); C += Ah*Bh + Ah*Bl + Al*Bh.
// ---------------------------------------------------------------------------
#define KT 16

__global__ __launch_bounds__(256)
void gemm_tc3(const float* __restrict__ A, const float* __restrict__ B,
              float* __restrict__ C, const float* __restrict__ bias,
              int M, int N, int K)
{
    __shared__ float2 As2[KT][130];   // [k][m] (hi,lo), padded
    __shared__ float2 Bs2[KT][66];    // [k][n] (hi,lo), padded

    const int t    = threadIdx.x;
    const int lane = t & 31;
    const int w    = t >> 5;
    const int g    = lane >> 2;
    const int tig  = lane & 3;
    const int wm   = w >> 1;          // 0..3
    const int wn   = w & 1;           // 0..1
    const int m_cta = blockIdx.y * 128;
    const int n_cta = blockIdx.x * 64;

    FragC c[2][4];
#pragma unroll
    for (int i = 0; i < 2; i++)
#pragma unroll
        for (int j = 0; j < 4; j++) { c[i][j].x = c[i][j].y = c[i][j].z = c[i][j].w = 0.f; }

    for (int k0 = 0; k0 < K; k0 += KT) {
        __syncthreads();
        // ---- stage A tile (128 x 16) with hi/lo split: 512 float4 slots ----
#pragma unroll
        for (int u = 0; u < 2; u++) {
            int idx = t + u * 256;
            int m  = idx >> 2;
            int cc = idx & 3;
            float4 av = *(const float4*)&A[(size_t)(m_cta + m) * K + k0 + cc * 4];
#pragma unroll
            for (int i = 0; i < 4; i++) {
                float v  = ((float*)&av)[i];
                uint32_t hu = f2tf32(v);
                float lo = v - __uint_as_float(hu);
                As2[cc * 4 + i][m] = make_float2(__uint_as_float(hu),
                                                 __uint_as_float(f2tf32(lo)));
            }
        }
        // ---- stage B tile (16 x 64): 256 float4 slots ----
        {
            int kr = t >> 4;
            int c4 = t & 15;
            float4 bv = *(const float4*)&B[(size_t)(k0 + kr) * N + n_cta + c4 * 4];
#pragma unroll
            for (int i = 0; i < 4; i++) {
                float v  = ((float*)&bv)[i];
                uint32_t hu = f2tf32(v);
                float lo = v - __uint_as_float(hu);
                Bs2[kr][c4 * 4 + i] = make_float2(__uint_as_float(hu),
                                                  __uint_as_float(f2tf32(lo)));
            }
        }
        __syncthreads();

#pragma unroll
        for (int kk = 0; kk < KT; kk += 8) {
            uint32_t ah[2][4], al[2][4];
#pragma unroll
            for (int mf = 0; mf < 2; mf++) {
                int mr = wm * 32 + mf * 16 + g;
                float2 p00 = As2[kk + tig][mr];
                float2 p10 = As2[kk + tig][mr + 8];
                float2 p01 = As2[kk + tig + 4][mr];
                float2 p11 = As2[kk + tig + 4][mr + 8];
                ah[mf][0] = __float_as_uint(p00.x); al[mf][0] = __float_as_uint(p00.y);
                ah[mf][1] = __float_as_uint(p10.x); al[mf][1] = __float_as_uint(p10.y);
                ah[mf][2] = __float_as_uint(p01.x); al[mf][2] = __float_as_uint(p01.y);
                ah[mf][3] = __float_as_uint(p11.x); al[mf][3] = __float_as_uint(p11.y);
            }
            uint32_t bh[4][2], bl[4][2];
#pragma unroll
            for (int nf = 0; nf < 4; nf++) {
                int nc0 = wn * 32 + nf * 8 + g;
                float2 q0 = Bs2[kk + tig][nc0];
                float2 q1 = Bs2[kk + tig + 4][nc0];
                bh[nf][0] = __float_as_uint(q0.x); bl[nf][0] = __float_as_uint(q0.y);
                bh[nf][1] = __float_as_uint(q1.x); bl[nf][1] = __float_as_uint(q1.y);
            }
#pragma unroll
            for (int mf = 0; mf < 2; mf++)
#pragma unroll
                for (int nf = 0; nf < 4; nf++) {
                    mma_tf32(c[mf][nf], ah[mf][0], ah[mf][1], ah[mf][2], ah[mf][3],
                             bh[nf][0], bh[nf][1], c[mf][nf]);
                    mma_tf32(c[mf][nf], ah[mf][0], ah[mf][1], ah[mf][2], ah[mf][3],
                             bl[nf][0], bl[nf][1], c[mf][nf]);
                    mma_tf32(c[mf][nf], al[mf][0], al[mf][1], al[mf][2], al[mf][3],
                             bh[nf][0], bh[nf][1], c[mf][nf]);
                }
        }
    }

    // ---- epilogue ----
#pragma unroll
    for (int mf = 0; mf < 2; mf++) {
        int mr = m_cta + wm * 32 + mf * 16 + g;
#pragma unroll
        for (int nf = 0; nf < 4; nf++) {
            int nc0 = n_cta + wn * 32 + nf * 8 + 2 * tig;
            float b0 = 0.f, b1 = 0.f;
            if (bias) { b0 = bias[nc0]; b1 = bias[nc0 + 1]; }
            float2 lo_pair = make_float2(c[mf][nf].x + b0, c[mf][nf].y + b1);
            float2 hi_pair = make_float2(c[mf][nf].z + b0, c[mf][nf].w + b1);
            *(float2*)&C[(size_t)mr * N + nc0]       = lo_pair;
            *(float2*)&C[(size_t)(mr + 8) * N + nc0] = hi_pair;
        }
    }
}

// ---------------------------------------------------------------------------
// Causal flash attention, tf32 tensor cores, v2 (fixed staging count).
// Grid: (S/128, HEADS) with longest-first ordering; 256 threads (8 warps).
// Warp w owns q-rows [qt*128 + w*16, +16). K/V tiles 64x64 in smem (stride 68).
// P (probs) never touches smem: C-layout -> A-layout via register shuffles.
// ---------------------------------------------------------------------------
#define KVSTRIDE 68

__global__ __launch_bounds__(256)
void attn_tc2(const float* __restrict__ Q, const float* __restrict__ K,
              const float* __restrict__ V, float* __restrict__ O)
{
    __shared__ float Ksm[64 * KVSTRIDE];
    __shared__ float Vsm[64 * KVSTRIDE];

    const int t    = threadIdx.x;
    const int w    = t >> 5;
    const int lane = t & 31;
    const int g    = lane >> 2;
    const int tig  = lane & 3;
    const int qt   = gridDim.x - 1 - blockIdx.x;   // longest CTAs first
    const int h    = blockIdx.y;

    const int qbase = qt * 128;
    const int row0  = qbase + w * 16 + g;
    const int row1  = row0 + 8;
    const int wrow_max = qbase + w * 16 + 15;

    // ---- resident Q fragments (tf32): 8 k-chunks x 4 regs ----
    uint32_t qa[8][4];
    {
        const float* q0 = &Q[(size_t)row0 * EMBED + h * HDIM];
        const float* q1 = &Q[(size_t)row1 * EMBED + h * HDIM];
#pragma unroll
        for (int kc = 0; kc < 8; kc++) {
            qa[kc][0] = f2tf32(q0[kc * 8 + tig]);
            qa[kc][1] = f2tf32(q1[kc * 8 + tig]);
            qa[kc][2] = f2tf32(q0[kc * 8 + tig + 4]);
            qa[kc][3] = f2tf32(q1[kc * 8 + tig + 4]);
        }
    }

    FragC oacc[8];
#pragma unroll
    for (int nc = 0; nc < 8; nc++) { oacc[nc].x = oacc[nc].y = oacc[nc].z = oacc[nc].w = 0.f; }
    float m0 = -1e30f, m1 = -1e30f, l0 = 0.f, l1 = 0.f;

    const int jmax = (qbase + 127) >> 6;   // 2*qt + 1

    for (int j = 0; j <= jmax; j++) {
        const int kbase = j * 64;
        __syncthreads();
        // ---- cooperative K/V tile load + tf32 convert ----
        // 64 rows x 16 float4 = 1024 slots; 256 threads x 4 iters.  (BUG FIX:
        // round 3 used u<2 and only wrote rows 0..31.)
#pragma unroll
        for (int u = 0; u < 4; u++) {
            int id = t + u * 256;
            int r  = id >> 4;
            int c  = (id & 15) * 4;
            size_t goff = (size_t)(kbase + r) * EMBED + h * HDIM + c;
            float4 kv = *(const float4*)&K[goff];
            float4 vv = *(const float4*)&V[goff];
            float4 kc4, vc4;
            kc4.x = __uint_as_float(f2tf32(kv.x));
            kc4.y = __uint_as_float(f2tf32(kv.y));
            kc4.z = __uint_as_float(f2tf32(kv.z));
            kc4.w = __uint_as_float(f2tf32(kv.w));
            vc4.x = __uint_as_float(f2tf32(vv.x));
            vc4.y = __uint_as_float(f2tf32(vv.y));
            vc4.z = __uint_as_float(f2tf32(vv.z));
            vc4.w = __uint_as_float(f2tf32(vv.w));
            *(float4*)&Ksm[r * KVSTRIDE + c] = kc4;
            *(float4*)&Vsm[r * KVSTRIDE + c] = vc4;
        }
        __syncthreads();

        if (kbase > wrow_max) continue;    // fully masked for this warp

        // ---- S = Q K^T (16x64 per warp) ----
        FragC st[8];
#pragma unroll
        for (int nc = 0; nc < 8; nc++) { st[nc].x = st[nc].y = st[nc].z = st[nc].w = 0.f; }
#pragma unroll
        for (int kc = 0; kc < 8; kc++) {
            const int d0 = kc * 8 + tig;
#pragma unroll
            for (int nc = 0; nc < 8; nc++) {
                const float* kr = &Ksm[(nc * 8 + g) * KVSTRIDE];
                uint32_t b0 = __float_as_uint(kr[d0]);
                uint32_t b1 = __float_as_uint(kr[d0 + 4]);
                mma_tf32(st[nc], qa[kc][0], qa[kc][1], qa[kc][2], qa[kc][3], b0, b1, st[nc]);
            }
        }

        // ---- scale + causal mask + online softmax ----
        const bool maskTile = (kbase + 63 > row0);
        const int  colb = kbase + 2 * tig;
        float tmax0 = -1e30f, tmax1 = -1e30f;
#pragma unroll
        for (int nc = 0; nc < 8; nc++) {
            int c0 = colb + nc * 8;
            float sx = st[nc].x * 0.125f;
            float sy = st[nc].y * 0.125f;
            float sz = st[nc].z * 0.125f;
            float sw = st[nc].w * 0.125f;
            if (maskTile) {
                if (c0     > row0) sx = -1e30f;
                if (c0 + 1 > row0) sy = -1e30f;
                if (c0     > row1) sz = -1e30f;
                if (c0 + 1 > row1) sw = -1e30f;
            }
            st[nc].x = sx; st[nc].y = sy; st[nc].z = sz; st[nc].w = sw;
            tmax0 = fmaxf(tmax0, fmaxf(sx, sy));
            tmax1 = fmaxf(tmax1, fmaxf(sz, sw));
        }
        tmax0 = fmaxf(tmax0, __shfl_xor_sync(0xffffffff, tmax0, 1));
        tmax0 = fmaxf(tmax0, __shfl_xor_sync(0xffffffff, tmax0, 2));
        tmax1 = fmaxf(tmax1, __shfl_xor_sync(0xffffffff, tmax1, 1));
        tmax1 = fmaxf(tmax1, __shfl_xor_sync(0xffffffff, tmax1, 2));

        float m0n = fmaxf(m0, tmax0);
        float m1n = fmaxf(m1, tmax1);
        float cr0 = __expf(m0 - m0n);
        float cr1 = __expf(m1 - m1n);
        m0 = m0n; m1 = m1n;
        l0 *= cr0; l1 *= cr1;
#pragma unroll
        for (int nc = 0; nc < 8; nc++) {
            oacc[nc].x *= cr0; oacc[nc].y *= cr0;
            oacc[nc].z *= cr1; oacc[nc].w *= cr1;
        }

        // ---- exp + tf32 convert (keep in C-register layout) ----
        uint32_t pu[8][4];
        float sum0 = 0.f, sum1 = 0.f;
#pragma unroll
        for (int nc = 0; nc < 8; nc++) {
            float px = __expf(st[nc].x - m0n);
            float py = __expf(st[nc].y - m0n);
            float pz = __expf(st[nc].z - m1n);
            float pw = __expf(st[nc].w - m1n);
            sum0 += px + py;
            sum1 += pz + pw;
            pu[nc][0] = f2tf32(px);
            pu[nc][1] = f2tf32(py);
            pu[nc][2] = f2tf32(pz);
            pu[nc][3] = f2tf32(pw);
        }
        sum0 += __shfl_xor_sync(0xffffffff, sum0, 1);
        sum0 += __shfl_xor_sync(0xffffffff, sum0, 2);
        sum1 += __shfl_xor_sync(0xffffffff, sum1, 1);
        sum1 += __shfl_xor_sync(0xffffffff, sum1, 2);
        l0 += sum0; l1 += sum1;

        // ---- O += P V : C-layout -> A-layout via shuffles, then mma ----
        const int srcA = (g << 2) | (tig >> 1);
        const int srcB = srcA + 2;
        const bool odd = (tig & 1);
#pragma unroll
        for (int kc = 0; kc < 8; kc++) {
            uint32_t xA = __shfl_sync(0xffffffff, pu[kc][0], srcA);
            uint32_t yA = __shfl_sync(0xffffffff, pu[kc][1], srcA);
            uint32_t zA = __shfl_sync(0xffffffff, pu[kc][2], srcA);
            uint32_t wA = __shfl_sync(0xffffffff, pu[kc][3], srcA);
            uint32_t xB = __shfl_sync(0xffffffff, pu[kc][0], srcB);
            uint32_t yB = __shfl_sync(0xffffffff, pu[kc][1], srcB);
            uint32_t zB = __shfl_sync(0xffffffff, pu[kc][2], srcB);
            uint32_t wB = __shfl_sync(0xffffffff, pu[kc][3], srcB);
            uint32_t a0 = odd ? yA : xA;   // P(row0, kc*8+tig)
            uint32_t a1 = odd ? wA : zA;   // P(row1, kc*8+tig)
            uint32_t a2 = odd ? yB : xB;   // P(row0, kc*8+tig+4)
            uint32_t a3 = odd ? wB : zB;   // P(row1, kc*8+tig+4)

            const float* vr0 = &Vsm[(kc * 8 + tig) * KVSTRIDE];
            const float* vr1 = &Vsm[(kc * 8 + tig + 4) * KVSTRIDE];
#pragma unroll
            for (int nc = 0; nc < 8; nc++) {
                uint32_t b0 = __float_as_uint(vr0[nc * 8 + g]);
                uint32_t b1 = __float_as_uint(vr1[nc * 8 + g]);
                mma_tf32(oacc[nc], a0, a1, a2, a3, b0, b1, oacc[nc]);
            }
        }
    }

    // ---- epilogue ----
    float r0 = 1.f / l0;
    float r1 = 1.f / l1;
    float* o0 = &O[(size_t)row0 * EMBED + h * HDIM];
    float* o1 = &O[(size_t)row1 * EMBED + h * HDIM];
#pragma unroll
    for (int nc = 0; nc < 8; nc++) {
        float2 a, b;
        a.x = oacc[nc].x * r0; a.y = oacc[nc].y * r0;
        b.x = oacc[nc].z * r1; b.y = oacc[nc].w * r1;
        *(float2*)&o0[nc * 8 + 2 * tig] = a;
        *(float2*)&o1[nc * 8 + 2 * tig] = b;
    }
}

// ---------------------------------------------------------------------------
// Launch. Input order: values, keys, queries, mask, W_q, W_k, W_v, W_o, b_o
// ---------------------------------------------------------------------------
extern "C" void kernel_launch(void* const* d_in, const int* in_sizes, int n_in,
                              void* d_out, int out_size)
{
    const float* values  = (const float*)d_in[0];
    const float* keys    = (const float*)d_in[1];
    const float* queries = (const float*)d_in[2];
    // d_in[3] = mask: pure causal triu, handled analytically — never read
    const float* W_q = (const float*)d_in[4];
    const float* W_k = (const float*)d_in[5];
    const float* W_v = (const float*)d_in[6];
    const float* W_o = (const float*)d_in[7];
    const float* b_o = (const float*)d_in[8];
    float* out = (float*)d_out;

    float *Qp, *Kp, *Vp, *Op;
    cudaGetSymbolAddress((void**)&Qp, g_Q);
    cudaGetSymbolAddress((void**)&Kp, g_K);
    cudaGetSymbolAddress((void**)&Vp, g_V);
    cudaGetSymbolAddress((void**)&Op, g_O);

    dim3 gemm_grid(EMBED / 64, S_LEN / 128);    // (12, 32)
    gemm_tc3<<<gemm_grid, 256>>>(queries, W_q, Qp, nullptr, S_LEN, EMBED, EMBED);
    gemm_tc3<<<gemm_grid, 256>>>(keys,    W_k, Kp, nullptr, S_LEN, EMBED, EMBED);
    gemm_tc3<<<gemm_grid, 256>>>(values,  W_v, Vp, nullptr, S_LEN, EMBED, EMBED);

    dim3 attn_grid(S_LEN / 128, HEADS);         // (32, 12)
    attn_tc2<<<attn_grid, 256>>>(Qp, Kp, Vp, Op);

    gemm_tc3<<<gemm_grid, 256>>>(Op, W_o, out, b_o, S_LEN, EMBED, EMBED);
}